// round 14
// baseline (speedup 1.0000x reference)
#include <cuda_runtime.h>

#define NN    128
#define BATCH 2
#define LL    2048
#define CH    32          // chunk length S
#define NG    (LL/CH)     // 64 chunks per batch
#define NSC   8           // superchunks per batch (8 chunks each)
#define NT    512         // threads for split-K kernels
#define PIT   129         // smem pitch (conflict-free)

// ---- device scratch (no allocation allowed) ----
__device__ float g_Ad[NN*NN];
__device__ float g_Bd[NN];
__device__ float g_pow[2][NN*NN];       // squaring ping-pong (ends: Ad^256 in pow[0])
__device__ float g_M32[NN*NN];          // Ad^32 (saved mid-chain)
__device__ float g_h[BATCH*NG*NN];      // local chunk contributions
__device__ float g_h2[BATCH*NSC*NN];    // superchunk totals
__device__ float g_sbound[BATCH*NSC*NN];// state entering each superchunk
__device__ float g_bound[BATCH*NG*NN];  // state entering each chunk

// ============================================================
// Kernel 1: SETUP (one cluster launch: disc + Bd + 8 squarings).
// 8 CTAs x 1024 threads.
//  - rank 0: D&C triangular inverse of P1 = I - 0.5A (lower tri),
//    Ad = 2*Minv - I, Bd = Minv*B.
//  - all ranks: 8 squaring rounds (16 rows/block), cluster barriers.
//    it=4 result (Ad^32) also saved to g_M32; final (it=7) = Ad^256
//    lands in g_pow[0].
// ============================================================
__global__ __launch_bounds__(1024, 1) __cluster_dims__(8, 1, 1)
void k_setup(const float* __restrict__ A, const float* __restrict__ B) {
    extern __shared__ float sm[];
    int tid = threadIdx.x;
    unsigned rank;
    asm("mov.u32 %0, %%cluster_ctarank;" : "=r"(rank));

    if (rank == 0) {
        float* sP = sm;                 // NN*PIT
        float* sM = sm + NN*PIT;        // NN*PIT
        float* sT = sm + 2*NN*PIT;      // 4096 temp

        for (int idx = tid; idx < NN*NN; idx += 1024) {
            int i = idx >> 7, j = idx & (NN-1);
            float iv = (i == j) ? 1.0f : 0.0f;
            sP[i*PIT + j] = iv - 0.5f * A[idx];
            sM[i*PIT + j] = 0.0f;
        }
        __syncthreads();

        // base: 16 diagonal 8x8 blocks, forward substitution
        if (tid < 128) {
            int blk = tid >> 3, col = tid & 7;
            int b0 = blk * 8;
            float x[8];
            #pragma unroll
            for (int i = 0; i < 8; i++) x[i] = 0.0f;
            for (int i = col; i < 8; i++) {
                float v = (i == col) ? 1.0f : 0.0f;
                for (int k = col; k < i; k++)
                    v -= sP[(b0+i)*PIT + b0 + k] * x[k];
                x[i] = v / sP[(b0+i)*PIT + b0 + i];
            }
            #pragma unroll
            for (int i = 0; i < 8; i++)
                sM[(b0+i)*PIT + b0 + col] = x[i];
        }
        __syncthreads();

        // 4 combine levels
        for (int s = 8; s <= 64; s <<= 1) {
            int npairs = NN / (2*s);
            int total  = npairs * s * s;
            for (int idx = tid; idx < total; idx += 1024) {
                int p = idx / (s*s);
                int rem = idx - p*s*s;
                int i = rem / s, j = rem - i*s;
                int r0 = 2*p*s;
                float acc = 0.0f;
                #pragma unroll 4
                for (int k = 0; k < s; k++)
                    acc = fmaf(sM[(r0+s+i)*PIT + r0+s+k],
                               sP[(r0+s+k)*PIT + r0+j], acc);
                sT[idx] = acc;
            }
            __syncthreads();
            for (int idx = tid; idx < total; idx += 1024) {
                int p = idx / (s*s);
                int rem = idx - p*s*s;
                int i = rem / s, j = rem - i*s;
                int r0 = 2*p*s;
                float acc = 0.0f;
                const float* tp = sT + p*s*s + i*s;
                #pragma unroll 4
                for (int k = 0; k < s; k++)
                    acc = fmaf(tp[k], sM[(r0+k)*PIT + r0+j], acc);
                sM[(r0+s+i)*PIT + r0+j] = -acc;
            }
            __syncthreads();
        }

        for (int idx = tid; idx < NN*NN; idx += 1024) {
            int i = idx >> 7, j = idx & (NN-1);
            float m = sM[i*PIT + j];
            float ad = 2.0f * m - ((i == j) ? 1.0f : 0.0f);
            g_Ad[idx] = ad;
            g_pow[0][idx] = ad;
        }
        if (tid < NN) {
            float acc = 0.0f;
            for (int j = 0; j <= tid; j++)
                acc = fmaf(sM[tid*PIT + j], B[j], acc);
            g_Bd[tid] = acc;
        }
    }
    __threadfence();
    __syncthreads();
    asm volatile("barrier.cluster.arrive.aligned;" ::: "memory");
    asm volatile("barrier.cluster.wait.aligned;"   ::: "memory");

    // ---- 8 squarings: Ad^2..Ad^256; save Ad^32 at it==4 ----
    float*  sB  = sm;                   // reuse first 64KB
    float4* sB4 = (float4*)sB;
    for (int it = 0; it < 8; it++) {
        const float4* s4 = (const float4*)g_pow[it & 1];
        float* dst = g_pow[(it & 1) ^ 1];
        #pragma unroll
        for (int u = 0; u < 4; u++)
            sB4[tid + 1024*u] = __ldcg(s4 + tid + 1024*u);
        __syncthreads();
        if (tid < 512) {
            int row = rank*16 + (tid >> 5);
            int c4  = tid & 31;
            const float* ra = sB + row*NN;
            float4 acc = make_float4(0.f,0.f,0.f,0.f);
            #pragma unroll 8
            for (int k = 0; k < NN; k++) {
                float4 bv = sB4[k*32 + c4];
                float a0 = ra[k];
                acc.x = fmaf(a0, bv.x, acc.x);
                acc.y = fmaf(a0, bv.y, acc.y);
                acc.z = fmaf(a0, bv.z, acc.z);
                acc.w = fmaf(a0, bv.w, acc.w);
            }
            ((float4*)(dst + row*NN))[c4] = acc;
            if (it == 4)
                ((float4*)(g_M32 + row*NN))[c4] = acc;   // Ad^32
        }
        __threadfence();
        __syncthreads();
        asm volatile("barrier.cluster.arrive.aligned;" ::: "memory");
        asm volatile("barrier.cluster.wait.aligned;"   ::: "memory");
    }
}

// ============================================================
// Kernel 2: phase A, 512 threads, 4-way split-K.
// ============================================================
__global__ __launch_bounds__(NT, 1) void k_phaseA(const float* __restrict__ f) {
    extern __shared__ float sm[];
    float* sAd = sm;               // NN*PIT
    float* sc  = sAd + NN*PIT;     // NN
    float* sf  = sc + NN;          // CH
    float* sp  = sf + CH;          // NT partials
    int tid = threadIdx.x;
    int r = tid & (NN-1), q = tid >> 7;
    int g = blockIdx.x, b = blockIdx.y;

    for (int idx = tid; idx < NN*NN; idx += NT) {
        int i = idx >> 7, j = idx & (NN-1);
        sAd[i*PIT + j] = g_Ad[idx];
    }
    if (tid < CH) sf[tid] = f[b*LL + g*CH + tid];
    if (tid < NN) sc[tid] = 0.0f;
    __syncthreads();

    float a[32];
    #pragma unroll
    for (int u = 0; u < 32; u++) a[u] = sAd[r*PIT + 32*q + u];
    float bd = (q == 0) ? g_Bd[r] : 0.0f;

    float cn = 0.0f;
    for (int t = 0; t < CH; t++) {
        float acc0 = (q == 0) ? bd * sf[t] : 0.f;
        float acc1 = 0.f, acc2 = 0.f, acc3 = 0.f;
        const float4* sc4 = (const float4*)sc;
        #pragma unroll
        for (int u4 = 0; u4 < 8; u4++) {
            float4 v = sc4[8*q + u4];
            acc0 = fmaf(a[4*u4+0], v.x, acc0);
            acc1 = fmaf(a[4*u4+1], v.y, acc1);
            acc2 = fmaf(a[4*u4+2], v.z, acc2);
            acc3 = fmaf(a[4*u4+3], v.w, acc3);
        }
        sp[q*NN + r] = (acc0 + acc1) + (acc2 + acc3);
        __syncthreads();
        if (q == 0) {
            cn = (sp[r] + sp[NN+r]) + (sp[2*NN+r] + sp[3*NN+r]);
            sc[r] = cn;
        }
        __syncthreads();
    }
    if (q == 0) g_h[(b*NG + g)*NN + r] = cn;
}

// ============================================================
// Kernel 3: hierarchical boundary scan, 8 steps per launch.
// MODE 0 (B_a): per-superchunk totals from zero  (grid NSC x BATCH)
// MODE 1 (B_b): superchunk boundary scan w/ Ad^256 (grid BATCH)
// MODE 2 (B_c): rebuild per-chunk bounds from sbound (grid NSC x BATCH)
// ============================================================
template<int MODE>
__global__ __launch_bounds__(NT, 1) void k_scan8() {
    extern __shared__ float sm[];
    float* sM = sm;             // NN*PIT
    float* sh = sM + NN*PIT;    // 8*NN staged h
    float* sc = sh + 8*NN;      // NN
    float* sp = sc + NN;        // NT
    int tid = threadIdx.x;
    int r = tid & (NN-1), q = tid >> 7;
    int s = (MODE == 1) ? 0 : blockIdx.x;
    int b = (MODE == 1) ? blockIdx.x : blockIdx.y;

    const float* M = (MODE == 1) ? g_pow[0] : g_M32;   // Ad^256 or Ad^32
    const float* h = (MODE == 1) ? (g_h2 + b*NSC*NN)
                                 : (g_h + (b*NG + s*NSC)*NN);
    for (int idx = tid; idx < NN*NN; idx += NT) {
        int i = idx >> 7, j = idx & (NN-1);
        sM[i*PIT + j] = M[idx];
    }
    if (tid < 256) ((float4*)sh)[tid] = __ldg((const float4*)h + tid);
    if (tid < NN)
        sc[tid] = (MODE == 2) ? g_sbound[(b*NSC + s)*NN + tid] : 0.0f;
    __syncthreads();

    float a[32];
    #pragma unroll
    for (int u = 0; u < 32; u++) a[u] = sM[r*PIT + 32*q + u];

    float cn = (MODE == 2) ? sc[r] : 0.0f;
    for (int g = 0; g < 8; g++) {
        if (MODE == 1 && q == 0) g_sbound[(b*NSC + g)*NN + r] = cn;
        if (MODE == 2 && q == 0) g_bound[(b*NG + s*NSC + g)*NN + r] = cn;
        float acc0 = (q == 0) ? sh[g*NN + r] : 0.f;
        float acc1 = 0.f, acc2 = 0.f, acc3 = 0.f;
        const float4* sc4 = (const float4*)sc;
        #pragma unroll
        for (int u4 = 0; u4 < 8; u4++) {
            float4 v = sc4[8*q + u4];
            acc0 = fmaf(a[4*u4+0], v.x, acc0);
            acc1 = fmaf(a[4*u4+1], v.y, acc1);
            acc2 = fmaf(a[4*u4+2], v.z, acc2);
            acc3 = fmaf(a[4*u4+3], v.w, acc3);
        }
        sp[q*NN + r] = (acc0 + acc1) + (acc2 + acc3);
        __syncthreads();
        if (q == 0) {
            cn = (sp[r] + sp[NN+r]) + (sp[2*NN+r] + sp[3*NN+r]);
            sc[r] = cn;
        }
        __syncthreads();
    }
    if (MODE == 0 && q == 0) g_h2[(b*NSC + s)*NN + r] = cn;
}

// ============================================================
// Kernel 4: FUSED phase C + expand, TWO-PASS (measured 53.5us).
// ============================================================
__global__ __launch_bounds__(NT, 1) void k_fusedC(const float* __restrict__ f,
                                                  const float* __restrict__ Cv,
                                                  const float* __restrict__ Dv,
                                                  float* __restrict__ ys,
                                                  float* __restrict__ cfin) {
    extern __shared__ float sm[];
    float* sAd = sm;               // NN*PIT
    float* sSt = sAd + NN*PIT;     // CH*NN states
    float* sc  = sSt + CH*NN;      // NN current state
    float* sf  = sc + NN;          // CH
    float* sC  = sf + CH;          // NN
    float* sp  = sC + NN;          // NT
    int tid = threadIdx.x;
    int r = tid & (NN-1), q = tid >> 7;
    int g = blockIdx.x, b = blockIdx.y;

    for (int idx = tid; idx < NN*NN; idx += NT) {
        int i = idx >> 7, j = idx & (NN-1);
        sAd[i*PIT + j] = g_Ad[idx];
    }
    if (tid < CH) sf[tid] = f[b*LL + g*CH + tid];
    if (tid < NN) {
        sC[tid] = Cv[tid];
        sc[tid] = g_bound[(b*NG + g)*NN + tid];
    }
    __syncthreads();

    float a[32];
    #pragma unroll
    for (int u = 0; u < 32; u++) a[u] = sAd[r*PIT + 32*q + u];
    float bd  = (q == 0) ? g_Bd[r] : 0.0f;
    float dv0 = Dv[0];

    // ---- pass 1: recurrence into sSt ----
    for (int t = 0; t < CH; t++) {
        float acc0 = (q == 0) ? bd * sf[t] : 0.f;
        float acc1 = 0.f, acc2 = 0.f, acc3 = 0.f;
        const float4* sc4 = (const float4*)sc;
        #pragma unroll
        for (int u4 = 0; u4 < 8; u4++) {
            float4 v = sc4[8*q + u4];
            acc0 = fmaf(a[4*u4+0], v.x, acc0);
            acc1 = fmaf(a[4*u4+1], v.y, acc1);
            acc2 = fmaf(a[4*u4+2], v.z, acc2);
            acc3 = fmaf(a[4*u4+3], v.w, acc3);
        }
        sp[q*NN + r] = (acc0 + acc1) + (acc2 + acc3);
        __syncthreads();
        if (q == 0) {
            float cn = (sp[r] + sp[NN+r]) + (sp[2*NN+r] + sp[3*NN+r]);
            sc[r] = cn;
            sSt[t*NN + r] = cn;
        }
        __syncthreads();
    }

    // ---- pass 2: barrier-free streaming store ----
    float cn_[8];
    int nb = tid >> 5;
    #pragma unroll
    for (int it = 0; it < 8; it++) cn_[it] = sC[nb + 16*it];
    int lane = tid & 31;
    float4* outbase = (float4*)(ys + (size_t)(b*LL + g*CH) * NN * NN);
    const float4* st4 = (const float4*)sSt;

    for (int t = 0; t < CH; t++) {
        float4 cv = st4[t*(NN/4) + lane];
        float  df = dv0 * sf[t];
        float4* out = outbase + (size_t)t * (NN*NN/4);
        #pragma unroll
        for (int it = 0; it < 8; it++) {
            int idx = tid + NT*it;
            float4 v;
            v.x = fmaf(cn_[it], cv.x, df);
            v.y = fmaf(cn_[it], cv.y, df);
            v.z = fmaf(cn_[it], cv.z, df);
            v.w = fmaf(cn_[it], cv.w, df);
            __stcs(&out[idx], v);
        }
    }
    if (cfin != nullptr && g == NG-1 && tid < NN)
        cfin[b*NN + tid] = sSt[(CH-1)*NN + tid];
}

// ============================================================
extern "C" void kernel_launch(void* const* d_in, const int* in_sizes, int n_in,
                              void* d_out, int out_size) {
    const float* f = (const float*)d_in[0];
    const float* A = (const float*)d_in[1];
    const float* B = (const float*)d_in[2];
    const float* C = (const float*)d_in[3];
    const float* D = (const float*)d_in[4];
    float* out = (float*)d_out;

    const long long ysz = (long long)BATCH * LL * NN * NN;   // 67108864
    const int cf = BATCH * NN;                               // 256
    float* cfin = nullptr;
    float* ys   = out;
    if ((long long)out_size == ysz + cf) { cfin = out; ys = out + cf; }

    const int smem_setup = (2*NN*PIT + 4096)*4;              // 148480
    const int smem_pA    = (NN*PIT + NN + CH + NT)*4;        // 68736
    const int smem_sc    = (NN*PIT + 8*NN + NN + NT)*4;      // 72704
    const int smem_fC    = (NN*PIT + CH*NN + NN + CH + NN + NT)*4; // 85632
    cudaFuncSetAttribute(k_setup,    cudaFuncAttributeMaxDynamicSharedMemorySize, smem_setup);
    cudaFuncSetAttribute(k_phaseA,   cudaFuncAttributeMaxDynamicSharedMemorySize, smem_pA);
    cudaFuncSetAttribute(k_scan8<0>, cudaFuncAttributeMaxDynamicSharedMemorySize, smem_sc);
    cudaFuncSetAttribute(k_scan8<1>, cudaFuncAttributeMaxDynamicSharedMemorySize, smem_sc);
    cudaFuncSetAttribute(k_scan8<2>, cudaFuncAttributeMaxDynamicSharedMemorySize, smem_sc);
    cudaFuncSetAttribute(k_fusedC,   cudaFuncAttributeMaxDynamicSharedMemorySize, smem_fC);

    // 1) setup: disc + Bd + Ad^{2..256} (one cluster launch)
    k_setup<<<8, 1024, smem_setup>>>(A, B);
    // 2) phase A — local chunk contributions
    dim3 gA(NG, BATCH);
    k_phaseA<<<gA, NT, smem_pA>>>(f);
    // 3) hierarchical boundary scan: 24 serial steps total
    dim3 gS(NSC, BATCH);
    k_scan8<0><<<gS, NT, smem_sc>>>();       // superchunk totals (parallel)
    k_scan8<1><<<BATCH, NT, smem_sc>>>();    // superchunk boundaries (Ad^256)
    k_scan8<2><<<gS, NT, smem_sc>>>();       // per-chunk bounds (parallel)
    // 4) fused phase C + expand (two-pass streaming store)
    k_fusedC<<<gA, NT, smem_fC>>>(f, C, D, ys, cfin);
}

// round 15
// speedup vs baseline: 1.2083x; 1.2083x over previous
#include <cuda_runtime.h>

#define NN    128
#define BATCH 2
#define LL    2048
#define CH    32          // chunk length S
#define NG    (LL/CH)     // 64 chunks per batch
#define NT    512         // threads for split-K kernels
#define PIT   129         // smem pitch (conflict-free)

// ---- device scratch (no allocation allowed) ----
__device__ float g_Ad[NN*NN];
__device__ float g_Bd[NN];
__device__ float g_pow[2][NN*NN];      // for Ad^S via squaring
__device__ float g_h[BATCH*NG*NN];     // local chunk contributions
__device__ float g_bound[BATCH*NG*NN]; // state entering each chunk

// ============================================================
// Kernel 1: discretize via divide-and-conquer triangular inverse.
// P1 = I - 0.5A is LOWER TRIANGULAR.  (R8 version, known-good)
// ============================================================
__global__ __launch_bounds__(1024, 1) void k_disc(const float* __restrict__ A,
                                                  const float* __restrict__ B) {
    extern __shared__ float sm[];
    float* sP = sm;                 // NN*PIT
    float* sM = sm + NN*PIT;        // NN*PIT
    float* sT = sm + 2*NN*PIT;      // 4096 temp
    int tid = threadIdx.x;

    for (int idx = tid; idx < NN*NN; idx += 1024) {
        int i = idx >> 7, j = idx & (NN-1);
        float iv = (i == j) ? 1.0f : 0.0f;
        sP[i*PIT + j] = iv - 0.5f * A[idx];
        sM[i*PIT + j] = 0.0f;
    }
    __syncthreads();

    if (tid < 128) {
        int blk = tid >> 3, col = tid & 7;
        int b0 = blk * 8;
        float x[8];
        #pragma unroll
        for (int i = 0; i < 8; i++) x[i] = 0.0f;
        for (int i = col; i < 8; i++) {
            float v = (i == col) ? 1.0f : 0.0f;
            for (int k = col; k < i; k++)
                v -= sP[(b0+i)*PIT + b0 + k] * x[k];
            x[i] = v / sP[(b0+i)*PIT + b0 + i];
        }
        #pragma unroll
        for (int i = 0; i < 8; i++)
            sM[(b0+i)*PIT + b0 + col] = x[i];
    }
    __syncthreads();

    for (int s = 8; s <= 64; s <<= 1) {
        int npairs = NN / (2*s);
        int total  = npairs * s * s;
        for (int idx = tid; idx < total; idx += 1024) {
            int p = idx / (s*s);
            int rem = idx - p*s*s;
            int i = rem / s, j = rem - i*s;
            int r0 = 2*p*s;
            float acc = 0.0f;
            for (int k = 0; k < s; k++)
                acc = fmaf(sM[(r0+s+i)*PIT + r0+s+k],
                           sP[(r0+s+k)*PIT + r0+j], acc);
            sT[idx] = acc;
        }
        __syncthreads();
        for (int idx = tid; idx < total; idx += 1024) {
            int p = idx / (s*s);
            int rem = idx - p*s*s;
            int i = rem / s, j = rem - i*s;
            int r0 = 2*p*s;
            float acc = 0.0f;
            const float* tp = sT + p*s*s + i*s;
            for (int k = 0; k < s; k++)
                acc = fmaf(tp[k], sM[(r0+k)*PIT + r0+j], acc);
            sM[(r0+s+i)*PIT + r0+j] = -acc;
        }
        __syncthreads();
    }

    for (int idx = tid; idx < NN*NN; idx += 1024) {
        int i = idx >> 7, j = idx & (NN-1);
        float m = sM[i*PIT + j];
        float ad = 2.0f * m - ((i == j) ? 1.0f : 0.0f);
        g_Ad[idx] = ad;
        g_pow[0][idx] = ad;
    }
    if (tid < NN) {
        float acc = 0.0f;
        for (int j = 0; j <= tid; j++)
            acc = fmaf(sM[tid*PIT + j], B[j], acc);
        g_Bd[tid] = acc;
    }
}

// ============================================================
// Kernel 2: matrix squaring, SMEM-staged (R8 version, 5.6us meas).
// 128 blocks x 128 threads; stage all of src, compute one row.
// ============================================================
__global__ __launch_bounds__(NN, 1) void k_sq(int srcSel, int dstSel) {
    extern __shared__ float smq[];    // NN*NN
    float* sB = smq;
    const float4* s4 = (const float4*)g_pow[srcSel];
    float* __restrict__ dst = g_pow[dstSel];
    int i = blockIdx.x, tid = threadIdx.x;
    float4* sB4 = (float4*)sB;
    #pragma unroll
    for (int u = 0; u < 32; u++)
        sB4[tid + NN*u] = __ldg(s4 + tid + NN*u);   // 32 LDG.128 in flight
    __syncthreads();
    const float* arow = sB + i*NN;
    float acc0 = 0.f, acc1 = 0.f, acc2 = 0.f, acc3 = 0.f;
    #pragma unroll 16
    for (int k = 0; k < NN; k += 4) {
        acc0 = fmaf(arow[k+0], sB[(k+0)*NN + tid], acc0);
        acc1 = fmaf(arow[k+1], sB[(k+1)*NN + tid], acc1);
        acc2 = fmaf(arow[k+2], sB[(k+2)*NN + tid], acc2);
        acc3 = fmaf(arow[k+3], sB[(k+3)*NN + tid], acc3);
    }
    dst[i*NN + tid] = (acc0 + acc1) + (acc2 + acc3);
}

// ============================================================
// Kernel 3: phase A, 512 threads, 4-way split-K (R8 version).
// ============================================================
__global__ __launch_bounds__(NT, 1) void k_phaseA(const float* __restrict__ f) {
    extern __shared__ float sm[];
    float* sAd = sm;               // NN*PIT
    float* sc  = sAd + NN*PIT;     // NN
    float* sf  = sc + NN;          // CH
    float* sp  = sf + CH;          // NT partials
    int tid = threadIdx.x;
    int r = tid & (NN-1), q = tid >> 7;
    int g = blockIdx.x, b = blockIdx.y;

    for (int idx = tid; idx < NN*NN; idx += NT) {
        int i = idx >> 7, j = idx & (NN-1);
        sAd[i*PIT + j] = g_Ad[idx];
    }
    if (tid < CH) sf[tid] = f[b*LL + g*CH + tid];
    if (tid < NN) sc[tid] = 0.0f;
    __syncthreads();

    float a[32];
    #pragma unroll
    for (int u = 0; u < 32; u++) a[u] = sAd[r*PIT + 32*q + u];
    float bd = (q == 0) ? g_Bd[r] : 0.0f;

    float cn = 0.0f;
    for (int t = 0; t < CH; t++) {
        float acc0 = (q == 0) ? bd * sf[t] : 0.f;
        float acc1 = 0.f, acc2 = 0.f, acc3 = 0.f;
        const float4* sc4 = (const float4*)sc;
        #pragma unroll
        for (int u4 = 0; u4 < 8; u4++) {
            float4 v = sc4[8*q + u4];
            acc0 = fmaf(a[4*u4+0], v.x, acc0);
            acc1 = fmaf(a[4*u4+1], v.y, acc1);
            acc2 = fmaf(a[4*u4+2], v.z, acc2);
            acc3 = fmaf(a[4*u4+3], v.w, acc3);
        }
        sp[q*NN + r] = (acc0 + acc1) + (acc2 + acc3);
        __syncthreads();
        if (q == 0) {
            cn = (sp[r] + sp[NN+r]) + (sp[2*NN+r] + sp[3*NN+r]);
            sc[r] = cn;
        }
        __syncthreads();
    }
    if (q == 0) g_h[(b*NG + g)*NN + r] = cn;
}

// ============================================================
// Kernel 4: boundary prefix with PRE-STAGED h (R13 version, 27.3us).
// The 64-step serial loop touches ONLY smem/FMA/barriers.
// ============================================================
__global__ __launch_bounds__(NT, 1) void k_phaseB() {
    extern __shared__ float sm[];
    float* sA = sm;             // NN*PIT
    float* sh = sA + NN*PIT;    // NG*NN = 32KB staged h
    float* sc = sh + NG*NN;     // NN
    float* sp = sc + NN;        // NT
    int tid = threadIdx.x;
    int r = tid & (NN-1), q = tid >> 7;
    int b = blockIdx.x;
    const float* AdS = g_pow[1];   // Ad^32 after 5 squarings
    for (int idx = tid; idx < NN*NN; idx += NT) {
        int i = idx >> 7, j = idx & (NN-1);
        sA[i*PIT + j] = AdS[idx];
    }
    {
        const float4* hg = (const float4*)(g_h + b*NG*NN);
        float4* sh4 = (float4*)sh;
        #pragma unroll
        for (int u = 0; u < 4; u++)
            sh4[tid + NT*u] = __ldg(hg + tid + NT*u);
    }
    if (tid < NN) sc[tid] = 0.0f;
    __syncthreads();
    float a[32];
    #pragma unroll
    for (int u = 0; u < 32; u++) a[u] = sA[r*PIT + 32*q + u];

    float cn = 0.0f;
    for (int g = 0; g < NG; g++) {
        if (q == 0) g_bound[(b*NG + g)*NN + r] = cn;   // fire-and-forget
        float acc0 = (q == 0) ? sh[g*NN + r] : 0.f;    // smem, not global
        float acc1 = 0.f, acc2 = 0.f, acc3 = 0.f;
        const float4* sc4 = (const float4*)sc;
        #pragma unroll
        for (int u4 = 0; u4 < 8; u4++) {
            float4 v = sc4[8*q + u4];
            acc0 = fmaf(a[4*u4+0], v.x, acc0);
            acc1 = fmaf(a[4*u4+1], v.y, acc1);
            acc2 = fmaf(a[4*u4+2], v.z, acc2);
            acc3 = fmaf(a[4*u4+3], v.w, acc3);
        }
        sp[q*NN + r] = (acc0 + acc1) + (acc2 + acc3);
        __syncthreads();
        if (q == 0) {
            cn = (sp[r] + sp[NN+r]) + (sp[2*NN+r] + sp[3*NN+r]);
            sc[r] = cn;
        }
        __syncthreads();
    }
}

// ============================================================
// Kernel 5: FUSED phase C + expand, TWO-PASS (R8 version, 53.5us).
// ============================================================
__global__ __launch_bounds__(NT, 1) void k_fusedC(const float* __restrict__ f,
                                                  const float* __restrict__ Cv,
                                                  const float* __restrict__ Dv,
                                                  float* __restrict__ ys,
                                                  float* __restrict__ cfin) {
    extern __shared__ float sm[];
    float* sAd = sm;               // NN*PIT
    float* sSt = sAd + NN*PIT;     // CH*NN states
    float* sc  = sSt + CH*NN;      // NN current state
    float* sf  = sc + NN;          // CH
    float* sC  = sf + CH;          // NN
    float* sp  = sC + NN;          // NT
    int tid = threadIdx.x;
    int r = tid & (NN-1), q = tid >> 7;
    int g = blockIdx.x, b = blockIdx.y;

    for (int idx = tid; idx < NN*NN; idx += NT) {
        int i = idx >> 7, j = idx & (NN-1);
        sAd[i*PIT + j] = g_Ad[idx];
    }
    if (tid < CH) sf[tid] = f[b*LL + g*CH + tid];
    if (tid < NN) {
        sC[tid] = Cv[tid];
        sc[tid] = g_bound[(b*NG + g)*NN + tid];
    }
    __syncthreads();

    float a[32];
    #pragma unroll
    for (int u = 0; u < 32; u++) a[u] = sAd[r*PIT + 32*q + u];
    float bd  = (q == 0) ? g_Bd[r] : 0.0f;
    float dv0 = Dv[0];

    // ---- pass 1: recurrence into sSt ----
    for (int t = 0; t < CH; t++) {
        float acc0 = (q == 0) ? bd * sf[t] : 0.f;
        float acc1 = 0.f, acc2 = 0.f, acc3 = 0.f;
        const float4* sc4 = (const float4*)sc;
        #pragma unroll
        for (int u4 = 0; u4 < 8; u4++) {
            float4 v = sc4[8*q + u4];
            acc0 = fmaf(a[4*u4+0], v.x, acc0);
            acc1 = fmaf(a[4*u4+1], v.y, acc1);
            acc2 = fmaf(a[4*u4+2], v.z, acc2);
            acc3 = fmaf(a[4*u4+3], v.w, acc3);
        }
        sp[q*NN + r] = (acc0 + acc1) + (acc2 + acc3);
        __syncthreads();
        if (q == 0) {
            float cn = (sp[r] + sp[NN+r]) + (sp[2*NN+r] + sp[3*NN+r]);
            sc[r] = cn;
            sSt[t*NN + r] = cn;
        }
        __syncthreads();
    }

    // ---- pass 2: barrier-free streaming store ----
    float cn_[8];
    int nb = tid >> 5;
    #pragma unroll
    for (int it = 0; it < 8; it++) cn_[it] = sC[nb + 16*it];
    int lane = tid & 31;
    float4* outbase = (float4*)(ys + (size_t)(b*LL + g*CH) * NN * NN);
    const float4* st4 = (const float4*)sSt;

    for (int t = 0; t < CH; t++) {
        float4 cv = st4[t*(NN/4) + lane];
        float  df = dv0 * sf[t];
        float4* out = outbase + (size_t)t * (NN*NN/4);
        #pragma unroll
        for (int it = 0; it < 8; it++) {
            int idx = tid + NT*it;
            float4 v;
            v.x = fmaf(cn_[it], cv.x, df);
            v.y = fmaf(cn_[it], cv.y, df);
            v.z = fmaf(cn_[it], cv.z, df);
            v.w = fmaf(cn_[it], cv.w, df);
            __stcs(&out[idx], v);
        }
    }
    if (cfin != nullptr && g == NG-1 && tid < NN)
        cfin[b*NN + tid] = sSt[(CH-1)*NN + tid];
}

// ============================================================
extern "C" void kernel_launch(void* const* d_in, const int* in_sizes, int n_in,
                              void* d_out, int out_size) {
    const float* f = (const float*)d_in[0];
    const float* A = (const float*)d_in[1];
    const float* B = (const float*)d_in[2];
    const float* C = (const float*)d_in[3];
    const float* D = (const float*)d_in[4];
    float* out = (float*)d_out;

    const long long ysz = (long long)BATCH * LL * NN * NN;   // 67108864
    const int cf = BATCH * NN;                               // 256
    float* cfin = nullptr;
    float* ys   = out;
    if ((long long)out_size == ysz + cf) { cfin = out; ys = out + cf; }

    const int smem_disc = (2*NN*PIT + 4096)*4;               // 148480
    const int smem_sq   = NN*NN*4;                           // 65536
    const int smem_pA   = (NN*PIT + NN + CH + NT)*4;         // 68736
    const int smem_pB   = (NN*PIT + NG*NN + NN + NT)*4;      // 101376
    const int smem_fC   = (NN*PIT + CH*NN + NN + CH + NN + NT)*4; // 85632
    cudaFuncSetAttribute(k_disc,   cudaFuncAttributeMaxDynamicSharedMemorySize, smem_disc);
    cudaFuncSetAttribute(k_sq,     cudaFuncAttributeMaxDynamicSharedMemorySize, smem_sq);
    cudaFuncSetAttribute(k_phaseA, cudaFuncAttributeMaxDynamicSharedMemorySize, smem_pA);
    cudaFuncSetAttribute(k_phaseB, cudaFuncAttributeMaxDynamicSharedMemorySize, smem_pB);
    cudaFuncSetAttribute(k_fusedC, cudaFuncAttributeMaxDynamicSharedMemorySize, smem_fC);

    // 1) discretize (D&C triangular inverse)
    k_disc<<<1, 1024, smem_disc>>>(A, B);
    // 2) phase A — local chunk contributions
    dim3 gA(NG, BATCH);
    k_phaseA<<<gA, NT, smem_pA>>>(f);
    // 3) Ad^32 via 5 squarings
    k_sq<<<NN, NN, smem_sq>>>(0, 1);
    k_sq<<<NN, NN, smem_sq>>>(1, 0);
    k_sq<<<NN, NN, smem_sq>>>(0, 1);
    k_sq<<<NN, NN, smem_sq>>>(1, 0);
    k_sq<<<NN, NN, smem_sq>>>(0, 1);
    // 4) boundary prefix (h pre-staged in smem)
    k_phaseB<<<BATCH, NT, smem_pB>>>();
    // 5) fused phase C + expand (two-pass streaming store)
    k_fusedC<<<gA, NT, smem_fC>>>(f, C, D, ys, cfin);
}

// round 16
// speedup vs baseline: 1.3543x; 1.1208x over previous
#include <cuda_runtime.h>

#define NN    128
#define BATCH 2
#define LL    2048
#define CH    32          // chunk length S
#define NG    (LL/CH)     // 64 chunks per batch
#define NT    512         // threads for split-K kernels
#define PIT   129         // smem pitch (conflict-free)

// ---- device scratch (no allocation allowed) ----
__device__ float g_Ad[NN*NN];
__device__ float g_Bd[NN];
__device__ float g_pow[2][NN*NN];      // for Ad^S via squaring
__device__ float g_h[BATCH*NG*NN];     // local chunk contributions
__device__ float g_bound[BATCH*NG*NN]; // state entering each chunk

// ============================================================
// Kernel 1: discretize via divide-and-conquer triangular inverse.
// P1 = I - 0.5A is LOWER TRIANGULAR.  (R8 version, known-good)
// ============================================================
__global__ __launch_bounds__(1024, 1) void k_disc(const float* __restrict__ A,
                                                  const float* __restrict__ B) {
    extern __shared__ float sm[];
    float* sP = sm;                 // NN*PIT
    float* sM = sm + NN*PIT;        // NN*PIT
    float* sT = sm + 2*NN*PIT;      // 4096 temp
    int tid = threadIdx.x;

    for (int idx = tid; idx < NN*NN; idx += 1024) {
        int i = idx >> 7, j = idx & (NN-1);
        float iv = (i == j) ? 1.0f : 0.0f;
        sP[i*PIT + j] = iv - 0.5f * A[idx];
        sM[i*PIT + j] = 0.0f;
    }
    __syncthreads();

    if (tid < 128) {
        int blk = tid >> 3, col = tid & 7;
        int b0 = blk * 8;
        float x[8];
        #pragma unroll
        for (int i = 0; i < 8; i++) x[i] = 0.0f;
        for (int i = col; i < 8; i++) {
            float v = (i == col) ? 1.0f : 0.0f;
            for (int k = col; k < i; k++)
                v -= sP[(b0+i)*PIT + b0 + k] * x[k];
            x[i] = v / sP[(b0+i)*PIT + b0 + i];
        }
        #pragma unroll
        for (int i = 0; i < 8; i++)
            sM[(b0+i)*PIT + b0 + col] = x[i];
    }
    __syncthreads();

    for (int s = 8; s <= 64; s <<= 1) {
        int npairs = NN / (2*s);
        int total  = npairs * s * s;
        for (int idx = tid; idx < total; idx += 1024) {
            int p = idx / (s*s);
            int rem = idx - p*s*s;
            int i = rem / s, j = rem - i*s;
            int r0 = 2*p*s;
            float acc = 0.0f;
            for (int k = 0; k < s; k++)
                acc = fmaf(sM[(r0+s+i)*PIT + r0+s+k],
                           sP[(r0+s+k)*PIT + r0+j], acc);
            sT[idx] = acc;
        }
        __syncthreads();
        for (int idx = tid; idx < total; idx += 1024) {
            int p = idx / (s*s);
            int rem = idx - p*s*s;
            int i = rem / s, j = rem - i*s;
            int r0 = 2*p*s;
            float acc = 0.0f;
            const float* tp = sT + p*s*s + i*s;
            for (int k = 0; k < s; k++)
                acc = fmaf(tp[k], sM[(r0+k)*PIT + r0+j], acc);
            sM[(r0+s+i)*PIT + r0+j] = -acc;
        }
        __syncthreads();
    }

    for (int idx = tid; idx < NN*NN; idx += 1024) {
        int i = idx >> 7, j = idx & (NN-1);
        float m = sM[i*PIT + j];
        float ad = 2.0f * m - ((i == j) ? 1.0f : 0.0f);
        g_Ad[idx] = ad;
        g_pow[0][idx] = ad;
    }
    if (tid < NN) {
        float acc = 0.0f;
        for (int j = 0; j <= tid; j++)
            acc = fmaf(sM[tid*PIT + j], B[j], acc);
        g_Bd[tid] = acc;
    }
}

// ============================================================
// Kernel 2: matrix squaring, SMEM-staged (R8 version, 5.6us meas).
// ============================================================
__global__ __launch_bounds__(NN, 1) void k_sq(int srcSel, int dstSel) {
    extern __shared__ float smq[];    // NN*NN
    float* sB = smq;
    const float4* s4 = (const float4*)g_pow[srcSel];
    float* __restrict__ dst = g_pow[dstSel];
    int i = blockIdx.x, tid = threadIdx.x;
    float4* sB4 = (float4*)sB;
    #pragma unroll
    for (int u = 0; u < 32; u++)
        sB4[tid + NN*u] = __ldg(s4 + tid + NN*u);
    __syncthreads();
    const float* arow = sB + i*NN;
    float acc0 = 0.f, acc1 = 0.f, acc2 = 0.f, acc3 = 0.f;
    #pragma unroll 16
    for (int k = 0; k < NN; k += 4) {
        acc0 = fmaf(arow[k+0], sB[(k+0)*NN + tid], acc0);
        acc1 = fmaf(arow[k+1], sB[(k+1)*NN + tid], acc1);
        acc2 = fmaf(arow[k+2], sB[(k+2)*NN + tid], acc2);
        acc3 = fmaf(arow[k+3], sB[(k+3)*NN + tid], acc3);
    }
    dst[i*NN + tid] = (acc0 + acc1) + (acc2 + acc3);
}

// ============================================================
// Kernel 3: phase A, 512 threads, 4-way split-K (R8 version).
// ============================================================
__global__ __launch_bounds__(NT, 1) void k_phaseA(const float* __restrict__ f) {
    extern __shared__ float sm[];
    float* sAd = sm;               // NN*PIT
    float* sc  = sAd + NN*PIT;     // NN
    float* sf  = sc + NN;          // CH
    float* sp  = sf + CH;          // NT partials
    int tid = threadIdx.x;
    int r = tid & (NN-1), q = tid >> 7;
    int g = blockIdx.x, b = blockIdx.y;

    for (int idx = tid; idx < NN*NN; idx += NT) {
        int i = idx >> 7, j = idx & (NN-1);
        sAd[i*PIT + j] = g_Ad[idx];
    }
    if (tid < CH) sf[tid] = f[b*LL + g*CH + tid];
    if (tid < NN) sc[tid] = 0.0f;
    __syncthreads();

    float a[32];
    #pragma unroll
    for (int u = 0; u < 32; u++) a[u] = sAd[r*PIT + 32*q + u];
    float bd = (q == 0) ? g_Bd[r] : 0.0f;

    float cn = 0.0f;
    for (int t = 0; t < CH; t++) {
        float acc0 = (q == 0) ? bd * sf[t] : 0.f;
        float acc1 = 0.f, acc2 = 0.f, acc3 = 0.f;
        const float4* sc4 = (const float4*)sc;
        #pragma unroll
        for (int u4 = 0; u4 < 8; u4++) {
            float4 v = sc4[8*q + u4];
            acc0 = fmaf(a[4*u4+0], v.x, acc0);
            acc1 = fmaf(a[4*u4+1], v.y, acc1);
            acc2 = fmaf(a[4*u4+2], v.z, acc2);
            acc3 = fmaf(a[4*u4+3], v.w, acc3);
        }
        sp[q*NN + r] = (acc0 + acc1) + (acc2 + acc3);
        __syncthreads();
        if (q == 0) {
            cn = (sp[r] + sp[NN+r]) + (sp[2*NN+r] + sp[3*NN+r]);
            sc[r] = cn;
        }
        __syncthreads();
    }
    if (q == 0) g_h[(b*NG + g)*NN + r] = cn;
}

// ============================================================
// Kernel 4: boundary prefix with PRE-STAGED h (R13 version, 27.3us).
// ============================================================
__global__ __launch_bounds__(NT, 1) void k_phaseB() {
    extern __shared__ float sm[];
    float* sA = sm;             // NN*PIT
    float* sh = sA + NN*PIT;    // NG*NN = 32KB staged h
    float* sc = sh + NG*NN;     // NN
    float* sp = sc + NN;        // NT
    int tid = threadIdx.x;
    int r = tid & (NN-1), q = tid >> 7;
    int b = blockIdx.x;
    const float* AdS = g_pow[1];   // Ad^32 after 5 squarings
    for (int idx = tid; idx < NN*NN; idx += NT) {
        int i = idx >> 7, j = idx & (NN-1);
        sA[i*PIT + j] = AdS[idx];
    }
    {
        const float4* hg = (const float4*)(g_h + b*NG*NN);
        float4* sh4 = (float4*)sh;
        #pragma unroll
        for (int u = 0; u < 4; u++)
            sh4[tid + NT*u] = __ldg(hg + tid + NT*u);
    }
    if (tid < NN) sc[tid] = 0.0f;
    __syncthreads();
    float a[32];
    #pragma unroll
    for (int u = 0; u < 32; u++) a[u] = sA[r*PIT + 32*q + u];

    float cn = 0.0f;
    for (int g = 0; g < NG; g++) {
        if (q == 0) g_bound[(b*NG + g)*NN + r] = cn;
        float acc0 = (q == 0) ? sh[g*NN + r] : 0.f;
        float acc1 = 0.f, acc2 = 0.f, acc3 = 0.f;
        const float4* sc4 = (const float4*)sc;
        #pragma unroll
        for (int u4 = 0; u4 < 8; u4++) {
            float4 v = sc4[8*q + u4];
            acc0 = fmaf(a[4*u4+0], v.x, acc0);
            acc1 = fmaf(a[4*u4+1], v.y, acc1);
            acc2 = fmaf(a[4*u4+2], v.z, acc2);
            acc3 = fmaf(a[4*u4+3], v.w, acc3);
        }
        sp[q*NN + r] = (acc0 + acc1) + (acc2 + acc3);
        __syncthreads();
        if (q == 0) {
            cn = (sp[r] + sp[NN+r]) + (sp[2*NN+r] + sp[3*NN+r]);
            sc[r] = cn;
        }
        __syncthreads();
    }
}

// ============================================================
// Kernel 5: FUSED phase C + expand, WARP-SPECIALIZED.
// Producers (warps 0-7, 256 thr): recurrence, 2-way split-K per row,
//   double-buffered state, ONE named barrier (bar.sync 1,256) per step,
//   publish step counter via volatile smem flag.
// Consumers (warps 8-15, 256 thr): spin on flag, stream tile t
//   (1 LDS.128 + 16 STG.128 per thread, zero barriers).
// Stores overlap the recurrence -> approaches the pure store floor.
// ============================================================
__global__ __launch_bounds__(NT, 1) void k_fusedC(const float* __restrict__ f,
                                                  const float* __restrict__ Cv,
                                                  const float* __restrict__ Dv,
                                                  float* __restrict__ ys,
                                                  float* __restrict__ cfin) {
    extern __shared__ float sm[];
    float* sAd  = sm;               // NN*PIT
    float* sSt  = sAd + NN*PIT;     // CH*NN states
    float* sc0  = sSt + CH*NN;      // NN (state buffer 0)
    float* sc1  = sc0 + NN;         // NN (state buffer 1)
    float* sf   = sc1 + NN;         // CH
    float* sC   = sf + CH;          // NN
    int*  sFlag = (int*)(sC + NN);  // 1 (padded)
    int tid = threadIdx.x;
    int g = blockIdx.x, b = blockIdx.y;

    for (int idx = tid; idx < NN*NN; idx += NT) {
        int i = idx >> 7, j = idx & (NN-1);
        sAd[i*PIT + j] = g_Ad[idx];
    }
    if (tid < CH) sf[tid] = f[b*LL + g*CH + tid];
    if (tid < NN) {
        sC[tid]  = Cv[tid];
        sc0[tid] = g_bound[(b*NG + g)*NN + tid];
    }
    if (tid == 0) *sFlag = 0;
    __syncthreads();

    float dv0 = Dv[0];

    if (tid < 256) {
        // ---------------- producers ----------------
        int r = tid >> 1, h = tid & 1;       // row, k-half
        float a[64];
        #pragma unroll
        for (int u = 0; u < 64; u++) a[u] = sAd[r*PIT + 64*h + u];
        float bd = (h == 0) ? g_Bd[r] : 0.0f;
        float* bufs[2] = {sc0, sc1};
        float cn = 0.0f;

        #pragma unroll 2
        for (int t = 0; t < CH; t++) {
            const float4* sc4 = (const float4*)bufs[t & 1];
            float acc0 = (h == 0) ? bd * sf[t] : 0.f;
            float acc1 = 0.f, acc2 = 0.f, acc3 = 0.f;
            #pragma unroll
            for (int u4 = 0; u4 < 16; u4++) {
                float4 v = sc4[16*h + u4];
                acc0 = fmaf(a[4*u4+0], v.x, acc0);
                acc1 = fmaf(a[4*u4+1], v.y, acc1);
                acc2 = fmaf(a[4*u4+2], v.z, acc2);
                acc3 = fmaf(a[4*u4+3], v.w, acc3);
            }
            float val = (acc0 + acc1) + (acc2 + acc3);
            val += __shfl_xor_sync(0xffffffffu, val, 1);   // combine halves
            if (h == 0) {
                bufs[(t+1) & 1][r] = val;
                sSt[t*NN + r]      = val;
                cn = val;
            }
            asm volatile("bar.sync 1, 256;" ::: "memory");
            if (tid == 0) {
                __threadfence_block();
                ((volatile int*)sFlag)[0] = t + 1;
            }
        }
        if (cfin != nullptr && g == NG-1 && h == 0)
            cfin[b*NN + r] = cn;
    } else {
        // ---------------- consumers ----------------
        int ct    = tid - 256;       // 0..255
        int k4    = ct & 31;         // float4 column (constant per thread)
        int nbase = ct >> 5;         // 0..7
        float cn_[16];
        #pragma unroll
        for (int it = 0; it < 16; it++) cn_[it] = sC[nbase + 8*it];
        float4* outbase = (float4*)(ys + (size_t)(b*LL + g*CH) * NN * NN);
        const float4* st4 = (const float4*)sSt;

        for (int t = 0; t < CH; t++) {
            while (((volatile int*)sFlag)[0] <= t) { }
            __threadfence_block();
            float4 cv = st4[t*(NN/4) + k4];
            float  df = dv0 * sf[t];
            float4* out = outbase + (size_t)t * (NN*NN/4);
            #pragma unroll
            for (int it = 0; it < 16; it++) {
                int idx = ct + 256*it;
                float4 v;
                v.x = fmaf(cn_[it], cv.x, df);
                v.y = fmaf(cn_[it], cv.y, df);
                v.z = fmaf(cn_[it], cv.z, df);
                v.w = fmaf(cn_[it], cv.w, df);
                __stcs(&out[idx], v);
            }
        }
    }
}

// ============================================================
extern "C" void kernel_launch(void* const* d_in, const int* in_sizes, int n_in,
                              void* d_out, int out_size) {
    const float* f = (const float*)d_in[0];
    const float* A = (const float*)d_in[1];
    const float* B = (const float*)d_in[2];
    const float* C = (const float*)d_in[3];
    const float* D = (const float*)d_in[4];
    float* out = (float*)d_out;

    const long long ysz = (long long)BATCH * LL * NN * NN;   // 67108864
    const int cf = BATCH * NN;                               // 256
    float* cfin = nullptr;
    float* ys   = out;
    if ((long long)out_size == ysz + cf) { cfin = out; ys = out + cf; }

    const int smem_disc = (2*NN*PIT + 4096)*4;               // 148480
    const int smem_sq   = NN*NN*4;                           // 65536
    const int smem_pA   = (NN*PIT + NN + CH + NT)*4;         // 68736
    const int smem_pB   = (NN*PIT + NG*NN + NN + NT)*4;      // 101376
    const int smem_fC   = (NN*PIT + CH*NN + 2*NN + CH + NN + 16)*4; // ~84.3KB
    cudaFuncSetAttribute(k_disc,   cudaFuncAttributeMaxDynamicSharedMemorySize, smem_disc);
    cudaFuncSetAttribute(k_sq,     cudaFuncAttributeMaxDynamicSharedMemorySize, smem_sq);
    cudaFuncSetAttribute(k_phaseA, cudaFuncAttributeMaxDynamicSharedMemorySize, smem_pA);
    cudaFuncSetAttribute(k_phaseB, cudaFuncAttributeMaxDynamicSharedMemorySize, smem_pB);
    cudaFuncSetAttribute(k_fusedC, cudaFuncAttributeMaxDynamicSharedMemorySize, smem_fC);

    // 1) discretize (D&C triangular inverse)
    k_disc<<<1, 1024, smem_disc>>>(A, B);
    // 2) phase A — local chunk contributions
    dim3 gA(NG, BATCH);
    k_phaseA<<<gA, NT, smem_pA>>>(f);
    // 3) Ad^32 via 5 squarings
    k_sq<<<NN, NN, smem_sq>>>(0, 1);
    k_sq<<<NN, NN, smem_sq>>>(1, 0);
    k_sq<<<NN, NN, smem_sq>>>(0, 1);
    k_sq<<<NN, NN, smem_sq>>>(1, 0);
    k_sq<<<NN, NN, smem_sq>>>(0, 1);
    // 4) boundary prefix (h pre-staged in smem)
    k_phaseB<<<BATCH, NT, smem_pB>>>();
    // 5) fused phase C + expand (warp-specialized producer/consumer)
    k_fusedC<<<gA, NT, smem_fC>>>(f, C, D, ys, cfin);
}